// round 13
// baseline (speedup 1.0000x reference)
#include <cuda_runtime.h>
#include <cuda_fp16.h>
#include <cstdint>

#define BB     2048
#define TT     2049
#define SS     2048      // T-1
#define KK     8
#define CSZ    2         // cluster size
#define QT     1024      // timesteps per CTA
#define NTH    512       // threads per CTA
#define NW     16        // warps per CTA
#define WT     64        // timesteps per warp
#define NCH    4         // chunks per warp
#define CHT    16        // timesteps per chunk (2 lanes per t)
#define GAMMA_F 0.99f

// smem: wA,wM [NW*KK] f32 | sXin [KK] | red [NW]
#define SMEM_BYTES (2*NW*KK*4 + KK*4 + NW*4)

__device__ __forceinline__ uint32_t smem_u32(const void* p) {
    uint32_t a;
    asm("{ .reg .u64 t; cvta.to.shared.u64 t, %1; cvt.u32.u64 %0, t; }"
        : "=r"(a) : "l"(p));
    return a;
}

__global__ __launch_bounds__(NTH, 2) __cluster_dims__(CSZ, 1, 1)
void retrace_loss_kernel(const float* __restrict__ q,
                         const float* __restrict__ tq,
                         const float* __restrict__ tv,
                         const float* __restrict__ rw,
                         const float* __restrict__ olp,
                         const float* __restrict__ tlp,
                         float* __restrict__ out)
{
    extern __shared__ char smem[];
    float* wA   = (float*)smem;            // NW*KK
    float* wM   = wA + NW * KK;            // NW*KK
    float* sXin = wM + NW * KK;            // KK
    float* red  = sXin + KK;               // NW

    const int tid  = threadIdx.x;
    const int lane = tid & 31;
    const int w    = tid >> 5;       // warp 0..15, owns t_local [w*64, w*64+64)
    const int sl   = lane >> 1;      // timestep within chunk 0..15
    const int kg   = lane & 1;       // k-group (floats [kg*4, kg*4+4))

    uint32_t rank;
    asm("mov.u32 %0, %%cluster_ctarank;" : "=r"(rank));
    const int b = blockIdx.x >> 1;

    const size_t base3 = (size_t)b * TT * KK;
    const size_t base2 = (size_t)b * TT;
    const unsigned fullm = 0xFFFFFFFFu;

    // register-resident per-element state (relative to warp-region end)
    float4 As_reg[NCH];    // Asuf
    uint2  ms_reg[NCH];    // Msuf as 2x half2

    // running suffix relative to warp-region end
    float4 Ar = make_float4(0.f, 0.f, 0.f, 0.f);
    float4 Mr = make_float4(1.f, 1.f, 1.f, 1.f);

    #pragma unroll
    for (int ch = NCH - 1; ch >= 0; --ch) {
        const int tl = w * WT + ch * CHT + sl;          // local timestep
        const int t  = (int)rank * QT + tl;             // timestep in row
        const size_t o0 = base3 + (size_t)t * KK + kg * 4;

        // fully coalesced streaming loads (no q in phase 1)
        const float4 r4 = __ldcs((const float4*)(rw  + o0));
        const float4 v4 = __ldcs((const float4*)(tv  + o0 + KK));
        const float4 Q4 = __ldcs((const float4*)(tq  + o0 + KK));
        const float4 l4 = __ldcs((const float4*)(tlp + o0 + KK));
        const float  ol = olp[base2 + t + 1];

        const bool last = (t == SS - 1);
        const float sgn = last ? 1.0f : -1.0f;
        const float gm  = last ? 0.0f : GAMMA_F;

        float4 A, M;
        { float c = __expf(fminf(l4.x - ol, 0.f));
          A.x = fmaf(GAMMA_F, fmaf(sgn * c, Q4.x, v4.x), r4.x); M.x = gm * c; }
        { float c = __expf(fminf(l4.y - ol, 0.f));
          A.y = fmaf(GAMMA_F, fmaf(sgn * c, Q4.y, v4.y), r4.y); M.y = gm * c; }
        { float c = __expf(fminf(l4.z - ol, 0.f));
          A.z = fmaf(GAMMA_F, fmaf(sgn * c, Q4.z, v4.z), r4.z); M.z = gm * c; }
        { float c = __expf(fminf(l4.w - ol, 0.f));
          A.w = fmaf(GAMMA_F, fmaf(sgn * c, Q4.w, v4.w), r4.w); M.w = gm * c; }

        // warp suffix scan over 16 timesteps (lanes): x_sl = A + M * x_chunkend
        #pragma unroll
        for (int d = 1; d < 16; d <<= 1) {
            float4 Ao, Mo;
            Ao.x = __shfl_down_sync(fullm, A.x, 2 * d);
            Ao.y = __shfl_down_sync(fullm, A.y, 2 * d);
            Ao.z = __shfl_down_sync(fullm, A.z, 2 * d);
            Ao.w = __shfl_down_sync(fullm, A.w, 2 * d);
            Mo.x = __shfl_down_sync(fullm, M.x, 2 * d);
            Mo.y = __shfl_down_sync(fullm, M.y, 2 * d);
            Mo.z = __shfl_down_sync(fullm, M.z, 2 * d);
            Mo.w = __shfl_down_sync(fullm, M.w, 2 * d);
            if (sl + d < 16) {
                A.x = fmaf(M.x, Ao.x, A.x); M.x *= Mo.x;
                A.y = fmaf(M.y, Ao.y, A.y); M.y *= Mo.y;
                A.z = fmaf(M.z, Ao.z, A.z); M.z *= Mo.z;
                A.w = fmaf(M.w, Ao.w, A.w); M.w *= Mo.w;
            }
        }

        // full-chunk transform lives in lanes 0 (k0-3) / 1 (k4-7)
        float4 Af, Mf;
        Af.x = __shfl_sync(fullm, A.x, kg);
        Af.y = __shfl_sync(fullm, A.y, kg);
        Af.z = __shfl_sync(fullm, A.z, kg);
        Af.w = __shfl_sync(fullm, A.w, kg);
        Mf.x = __shfl_sync(fullm, M.x, kg);
        Mf.y = __shfl_sync(fullm, M.y, kg);
        Mf.z = __shfl_sync(fullm, M.z, kg);
        Mf.w = __shfl_sync(fullm, M.w, kg);

        // suffix relative to warp-region end: Asuf = A + M*Ar, Msuf = M*Mr
        float4 As, Ms;
        As.x = fmaf(M.x, Ar.x, A.x);  Ms.x = M.x * Mr.x;
        As.y = fmaf(M.y, Ar.y, A.y);  Ms.y = M.y * Mr.y;
        As.z = fmaf(M.z, Ar.z, A.z);  Ms.z = M.z * Mr.z;
        As.w = fmaf(M.w, Ar.w, A.w);  Ms.w = M.w * Mr.w;

        As_reg[ch] = As;
        __half2 h01 = __floats2half2_rn(Ms.x, Ms.y);
        __half2 h23 = __floats2half2_rn(Ms.z, Ms.w);
        ms_reg[ch].x = *(uint32_t*)&h01;
        ms_reg[ch].y = *(uint32_t*)&h23;

        // advance running suffix by the full chunk
        Ar.x = fmaf(Mf.x, Ar.x, Af.x);  Mr.x *= Mf.x;
        Ar.y = fmaf(Mf.y, Ar.y, Af.y);  Mr.y *= Mf.y;
        Ar.z = fmaf(Mf.z, Ar.z, Af.z);  Mr.z *= Mf.z;
        Ar.w = fmaf(Mf.w, Ar.w, Af.w);  Mr.w *= Mf.w;
    }

    // warp totals -> smem
    if (lane < 2) {
        *(float4*)(wA + w * KK + kg * 4) = Ar;
        *(float4*)(wM + w * KK + kg * 4) = Mr;
    }
    __syncthreads();

    // issue q loads NOW: they fly during combine + barrier (tail overlap)
    float4 q_reg[NCH];
    #pragma unroll
    for (int ch = 0; ch < NCH; ++ch) {
        const int tl = w * WT + ch * CHT + sl;
        const size_t o0 = base3 + (size_t)((int)rank * QT + tl) * KK + kg * 4;
        q_reg[ch] = __ldcs((const float4*)(q + o0));
    }

    // rank1: CTA total applied to 0 -> DSMEM seed for rank0
    if (rank == 1 && tid < KK) {
        float x = 0.0f;
        #pragma unroll
        for (int ww = NW - 1; ww >= 0; --ww)
            x = fmaf(wM[ww * KK + tid], x, wA[ww * KK + tid]);
        uint32_t laddr = smem_u32(&sXin[tid]);
        uint32_t raddr;
        asm("mapa.shared::cluster.u32 %0, %1, %2;" : "=r"(raddr) : "r"(laddr), "r"(0));
        asm volatile("st.shared::cluster.f32 [%0], %1;" :: "r"(raddr), "f"(x) : "memory");
    }

    // split cluster barrier: everyone arrives (release: publishes rank1's DSMEM
    // stores); only rank0 must wait here (it consumes the seed). rank1 defers its
    // wait to kernel end, where it is already satisfied -> no midpoint stall.
    asm volatile("barrier.cluster.arrive.aligned;" ::: "memory");
    if (rank == 0) {
        asm volatile("barrier.cluster.wait.aligned;" ::: "memory");
    }

    // carry at end of this warp's region: compose later warps onto cluster seed
    float4 x4;
    if (rank == 0) x4 = *(const float4*)(sXin + kg * 4);
    else           x4 = make_float4(0.f, 0.f, 0.f, 0.f);
    #pragma unroll
    for (int ww = NW - 1; ww > 0; --ww) {
        if (ww > w) {
            const float4 a4 = *(const float4*)(wA + ww * KK + kg * 4);
            const float4 m4 = *(const float4*)(wM + ww * KK + kg * 4);
            x4.x = fmaf(m4.x, x4.x, a4.x);
            x4.y = fmaf(m4.y, x4.y, a4.y);
            x4.z = fmaf(m4.z, x4.z, a4.z);
            x4.w = fmaf(m4.w, x4.w, a4.w);
        }
    }

    // Phase 2: d = q - (Asuf + Msuf * x4)
    float lsum = 0.0f;
    #pragma unroll
    for (int ch = 0; ch < NCH; ++ch) {
        const float4 a4 = As_reg[ch];
        const float4 q4 = q_reg[ch];
        const float2 m01 = __half22float2(*(const __half2*)&ms_reg[ch].x);
        const float2 m23 = __half22float2(*(const __half2*)&ms_reg[ch].y);

        float d, ad;
        d = q4.x - fmaf(m01.x, x4.x, a4.x); ad = fabsf(d);
        lsum += (ad < 1.0f) ? 0.5f * d * d : (ad - 0.5f);
        d = q4.y - fmaf(m01.y, x4.y, a4.y); ad = fabsf(d);
        lsum += (ad < 1.0f) ? 0.5f * d * d : (ad - 0.5f);
        d = q4.z - fmaf(m23.x, x4.z, a4.z); ad = fabsf(d);
        lsum += (ad < 1.0f) ? 0.5f * d * d : (ad - 0.5f);
        d = q4.w - fmaf(m23.y, x4.w, a4.w); ad = fabsf(d);
        lsum += (ad < 1.0f) ? 0.5f * d * d : (ad - 0.5f);
    }

    // reduce + atomic
    #pragma unroll
    for (int off = 16; off > 0; off >>= 1)
        lsum += __shfl_down_sync(fullm, lsum, off);
    if (lane == 0) red[w] = lsum;
    __syncthreads();
    if (tid < 32) {
        float v = (tid < NW) ? red[tid] : 0.0f;
        #pragma unroll
        for (int off = 8; off > 0; off >>= 1)
            v += __shfl_down_sync(fullm, v, off);
        if (tid == 0)
            atomicAdd(out, v * (1.0f / 33554432.0f));   // mean over 2048*2048*8
    }

    // rank1 completes the deferred cluster wait (already satisfied: all threads
    // arrived long ago). Keeps cluster exit semantics valid.
    if (rank == 1) {
        asm volatile("barrier.cluster.wait.aligned;" ::: "memory");
    }
}

extern "C" void kernel_launch(void* const* d_in, const int* in_sizes, int n_in,
                              void* d_out, int out_size)
{
    (void)in_sizes; (void)n_in; (void)out_size;
    const float* q   = (const float*)d_in[0];
    const float* tq  = (const float*)d_in[1];
    const float* tv  = (const float*)d_in[2];
    const float* rw  = (const float*)d_in[3];
    const float* olp = (const float*)d_in[4];
    const float* tlp = (const float*)d_in[5];
    float* out = (float*)d_out;

    cudaFuncSetAttribute(retrace_loss_kernel,
                         cudaFuncAttributeMaxDynamicSharedMemorySize,
                         SMEM_BYTES);

    cudaMemsetAsync(out, 0, sizeof(float));
    retrace_loss_kernel<<<BB * CSZ, NTH, SMEM_BYTES>>>(q, tq, tv, rw, olp, tlp, out);
}

// round 14
// speedup vs baseline: 1.1055x; 1.1055x over previous
#include <cuda_runtime.h>
#include <cuda_fp16.h>
#include <cstdint>

#define BB     2048
#define TT     2049
#define SS     2048      // T-1
#define KK     8
#define NTH    1024      // threads per CTA (one CTA per batch row)
#define NW     32        // warps per CTA
#define WT     64        // timesteps per warp
#define NCH    4         // chunks per warp
#define CHT    16        // timesteps per chunk (2 lanes per t)
#define GAMMA_F 0.99f

// smem (floats): b0A,b0M,b1A,b1M [NW*KK each] | red [NW]
#define SMEM_BYTES ((4*NW*KK + NW)*4)

__global__ __launch_bounds__(NTH, 1)
void retrace_loss_kernel(const float* __restrict__ q,
                         const float* __restrict__ tq,
                         const float* __restrict__ tv,
                         const float* __restrict__ rw,
                         const float* __restrict__ olp,
                         const float* __restrict__ tlp,
                         float* __restrict__ out)
{
    extern __shared__ char smem[];
    float* b0A  = (float*)smem;            // NW*KK
    float* b0M  = b0A + NW * KK;
    float* b1A  = b0M + NW * KK;
    float* b1M  = b1A + NW * KK;
    float* red  = b1M + NW * KK;           // NW

    const int tid  = threadIdx.x;
    const int lane = tid & 31;
    const int w    = tid >> 5;       // warp 0..31, owns t [w*64, w*64+64)
    const int sl   = lane >> 1;      // timestep within chunk 0..15
    const int kg   = lane & 1;       // k-group (floats [kg*4, kg*4+4))

    const int b = blockIdx.x;
    const size_t base3 = (size_t)b * TT * KK;
    const size_t base2 = (size_t)b * TT;
    const unsigned fullm = 0xFFFFFFFFu;

    // register-resident per-element state (relative to warp-region end)
    float4 As_reg[NCH];    // Asuf
    uint2  ms_reg[NCH];    // Msuf as 2x half2

    // running suffix relative to warp-region end
    float4 Ar = make_float4(0.f, 0.f, 0.f, 0.f);
    float4 Mr = make_float4(1.f, 1.f, 1.f, 1.f);

    #pragma unroll
    for (int ch = NCH - 1; ch >= 0; --ch) {
        const int t = w * WT + ch * CHT + sl;           // timestep in row
        const size_t o0 = base3 + (size_t)t * KK + kg * 4;

        // fully coalesced streaming loads (no q in phase 1)
        const float4 r4 = __ldcs((const float4*)(rw  + o0));
        const float4 v4 = __ldcs((const float4*)(tv  + o0 + KK));
        const float4 Q4 = __ldcs((const float4*)(tq  + o0 + KK));
        const float4 l4 = __ldcs((const float4*)(tlp + o0 + KK));
        const float  ol = olp[base2 + t + 1];

        const bool last = (t == SS - 1);
        const float sgn = last ? 1.0f : -1.0f;
        const float gm  = last ? 0.0f : GAMMA_F;

        float4 A, M;
        { float c = __expf(fminf(l4.x - ol, 0.f));
          A.x = fmaf(GAMMA_F, fmaf(sgn * c, Q4.x, v4.x), r4.x); M.x = gm * c; }
        { float c = __expf(fminf(l4.y - ol, 0.f));
          A.y = fmaf(GAMMA_F, fmaf(sgn * c, Q4.y, v4.y), r4.y); M.y = gm * c; }
        { float c = __expf(fminf(l4.z - ol, 0.f));
          A.z = fmaf(GAMMA_F, fmaf(sgn * c, Q4.z, v4.z), r4.z); M.z = gm * c; }
        { float c = __expf(fminf(l4.w - ol, 0.f));
          A.w = fmaf(GAMMA_F, fmaf(sgn * c, Q4.w, v4.w), r4.w); M.w = gm * c; }

        // warp suffix scan over 16 timesteps (lanes): x_sl = A + M * x_chunkend
        #pragma unroll
        for (int d = 1; d < 16; d <<= 1) {
            float4 Ao, Mo;
            Ao.x = __shfl_down_sync(fullm, A.x, 2 * d);
            Ao.y = __shfl_down_sync(fullm, A.y, 2 * d);
            Ao.z = __shfl_down_sync(fullm, A.z, 2 * d);
            Ao.w = __shfl_down_sync(fullm, A.w, 2 * d);
            Mo.x = __shfl_down_sync(fullm, M.x, 2 * d);
            Mo.y = __shfl_down_sync(fullm, M.y, 2 * d);
            Mo.z = __shfl_down_sync(fullm, M.z, 2 * d);
            Mo.w = __shfl_down_sync(fullm, M.w, 2 * d);
            if (sl + d < 16) {
                A.x = fmaf(M.x, Ao.x, A.x); M.x *= Mo.x;
                A.y = fmaf(M.y, Ao.y, A.y); M.y *= Mo.y;
                A.z = fmaf(M.z, Ao.z, A.z); M.z *= Mo.z;
                A.w = fmaf(M.w, Ao.w, A.w); M.w *= Mo.w;
            }
        }

        // full-chunk transform lives in lanes 0 (k0-3) / 1 (k4-7)
        float4 Af, Mf;
        Af.x = __shfl_sync(fullm, A.x, kg);
        Af.y = __shfl_sync(fullm, A.y, kg);
        Af.z = __shfl_sync(fullm, A.z, kg);
        Af.w = __shfl_sync(fullm, A.w, kg);
        Mf.x = __shfl_sync(fullm, M.x, kg);
        Mf.y = __shfl_sync(fullm, M.y, kg);
        Mf.z = __shfl_sync(fullm, M.z, kg);
        Mf.w = __shfl_sync(fullm, M.w, kg);

        // suffix relative to warp-region end: Asuf = A + M*Ar, Msuf = M*Mr
        float4 As, Ms;
        As.x = fmaf(M.x, Ar.x, A.x);  Ms.x = M.x * Mr.x;
        As.y = fmaf(M.y, Ar.y, A.y);  Ms.y = M.y * Mr.y;
        As.z = fmaf(M.z, Ar.z, A.z);  Ms.z = M.z * Mr.z;
        As.w = fmaf(M.w, Ar.w, A.w);  Ms.w = M.w * Mr.w;

        As_reg[ch] = As;
        __half2 h01 = __floats2half2_rn(Ms.x, Ms.y);
        __half2 h23 = __floats2half2_rn(Ms.z, Ms.w);
        ms_reg[ch].x = *(uint32_t*)&h01;
        ms_reg[ch].y = *(uint32_t*)&h23;

        // advance running suffix by the full chunk
        Ar.x = fmaf(Mf.x, Ar.x, Af.x);  Mr.x *= Mf.x;
        Ar.y = fmaf(Mf.y, Ar.y, Af.y);  Mr.y *= Mf.y;
        Ar.z = fmaf(Mf.z, Ar.z, Af.z);  Mr.z *= Mf.z;
        Ar.w = fmaf(Mf.w, Ar.w, Af.w);  Mr.w *= Mf.w;
    }

    // warp totals -> smem buffer 0
    if (lane < 2) {
        *(float4*)(b0A + w * KK + kg * 4) = Ar;
        *(float4*)(b0M + w * KK + kg * 4) = Mr;
    }
    __syncthreads();

    // issue q loads NOW: they fly during the smem scan (tail overlap)
    float4 q_reg[NCH];
    #pragma unroll
    for (int ch = 0; ch < NCH; ++ch) {
        const int t = w * WT + ch * CHT + sl;
        const size_t o0 = base3 + (size_t)t * KK + kg * 4;
        q_reg[ch] = __ldcs((const float4*)(q + o0));
    }

    // cooperative suffix scan over warp totals: S_w = T_w ∘ ... ∘ T_31
    #define SCAN_ROUND(SA, SM, DA, DM, D)                                     \
    do {                                                                      \
        if (tid < NW * KK) {                                                  \
            const int ww = tid >> 3;                                          \
            float a = SA[tid], m = SM[tid];                                   \
            if (ww + (D) < NW) {                                              \
                a = fmaf(m, SA[tid + (D) * KK], a);                           \
                m *= SM[tid + (D) * KK];                                      \
            }                                                                 \
            DA[tid] = a; DM[tid] = m;                                         \
        }                                                                     \
        __syncthreads();                                                      \
    } while (0)

    SCAN_ROUND(b0A, b0M, b1A, b1M, 1);
    SCAN_ROUND(b1A, b1M, b0A, b0M, 2);
    SCAN_ROUND(b0A, b0M, b1A, b1M, 4);
    SCAN_ROUND(b1A, b1M, b0A, b0M, 8);
    SCAN_ROUND(b0A, b0M, b1A, b1M, 16);
    // inclusive suffix S_w now in b1A/b1M

    // carry at end of this warp's region: seed is 0 (CTA covers full row),
    // so x4 = A-part of S_{w+1}; warp 31 -> 0.
    float4 x4;
    if (w < NW - 1) {
        x4 = *(const float4*)(b1A + (w + 1) * KK + kg * 4);
    } else {
        x4 = make_float4(0.f, 0.f, 0.f, 0.f);
    }

    // Phase 2: d = q - (Asuf + Msuf * x4)
    float lsum = 0.0f;
    #pragma unroll
    for (int ch = 0; ch < NCH; ++ch) {
        const float4 a4 = As_reg[ch];
        const float4 q4 = q_reg[ch];
        const float2 m01 = __half22float2(*(const __half2*)&ms_reg[ch].x);
        const float2 m23 = __half22float2(*(const __half2*)&ms_reg[ch].y);

        float d, ad;
        d = q4.x - fmaf(m01.x, x4.x, a4.x); ad = fabsf(d);
        lsum += (ad < 1.0f) ? 0.5f * d * d : (ad - 0.5f);
        d = q4.y - fmaf(m01.y, x4.y, a4.y); ad = fabsf(d);
        lsum += (ad < 1.0f) ? 0.5f * d * d : (ad - 0.5f);
        d = q4.z - fmaf(m23.x, x4.z, a4.z); ad = fabsf(d);
        lsum += (ad < 1.0f) ? 0.5f * d * d : (ad - 0.5f);
        d = q4.w - fmaf(m23.y, x4.w, a4.w); ad = fabsf(d);
        lsum += (ad < 1.0f) ? 0.5f * d * d : (ad - 0.5f);
    }

    // reduce + atomic
    #pragma unroll
    for (int off = 16; off > 0; off >>= 1)
        lsum += __shfl_down_sync(fullm, lsum, off);
    if (lane == 0) red[w] = lsum;
    __syncthreads();
    if (tid < 32) {
        float v = red[tid];
        #pragma unroll
        for (int off = 16; off > 0; off >>= 1)
            v += __shfl_down_sync(fullm, v, off);
        if (tid == 0)
            atomicAdd(out, v * (1.0f / 33554432.0f));   // mean over 2048*2048*8
    }
}

extern "C" void kernel_launch(void* const* d_in, const int* in_sizes, int n_in,
                              void* d_out, int out_size)
{
    (void)in_sizes; (void)n_in; (void)out_size;
    const float* q   = (const float*)d_in[0];
    const float* tq  = (const float*)d_in[1];
    const float* tv  = (const float*)d_in[2];
    const float* rw  = (const float*)d_in[3];
    const float* olp = (const float*)d_in[4];
    const float* tlp = (const float*)d_in[5];
    float* out = (float*)d_out;

    cudaFuncSetAttribute(retrace_loss_kernel,
                         cudaFuncAttributeMaxDynamicSharedMemorySize,
                         SMEM_BYTES);

    cudaMemsetAsync(out, 0, sizeof(float));
    retrace_loss_kernel<<<BB, NTH, SMEM_BYTES>>>(q, tq, tv, rw, olp, tlp, out);
}

// round 15
// speedup vs baseline: 1.1163x; 1.0098x over previous
#include <cuda_runtime.h>
#include <cuda_fp16.h>
#include <cstdint>

#define BB     2048
#define TT     2049
#define SS     2048      // T-1
#define KK     8
#define NTH    1024      // threads per CTA
#define NW     32        // warps per CTA
#define WT     64        // timesteps per warp
#define NCH    4         // chunks per warp
#define CHT    16        // timesteps per chunk (2 lanes per t)
#define GRID   152       // persistent CTAs (GB300: 152 SMs; robust to fewer via stealing)
#define GAMMA_F 0.99f

// smem (floats): b0A,b0M,b1A,b1M [NW*KK each] | red [NW]
#define SMEM_BYTES ((4*NW*KK + NW)*4)

__device__ unsigned int g_row_counter;

__global__ __launch_bounds__(NTH, 1)
void retrace_loss_kernel(const float* __restrict__ q,
                         const float* __restrict__ tq,
                         const float* __restrict__ tv,
                         const float* __restrict__ rw,
                         const float* __restrict__ olp,
                         const float* __restrict__ tlp,
                         float* __restrict__ out)
{
    extern __shared__ char smem[];
    float* b0A  = (float*)smem;            // NW*KK
    float* b0M  = b0A + NW * KK;
    float* b1A  = b0M + NW * KK;
    float* b1M  = b1A + NW * KK;
    float* red  = b1M + NW * KK;           // NW
    __shared__ unsigned int s_row;

    const int tid  = threadIdx.x;
    const int lane = tid & 31;
    const int w    = tid >> 5;       // warp 0..31, owns t [w*64, w*64+64)
    const int sl   = lane >> 1;      // timestep within chunk 0..15
    const int kg   = lane & 1;       // k-group (floats [kg*4, kg*4+4))
    const unsigned fullm = 0xFFFFFFFFu;

    float lsum = 0.0f;               // accumulated across all rows this thread touches

    for (;;) {
        if (tid == 0) s_row = atomicAdd(&g_row_counter, 1u);
        __syncthreads();
        const unsigned row = s_row;
        if (row >= BB) break;

        const size_t base3 = (size_t)row * TT * KK;
        const size_t base2 = (size_t)row * TT;

        // register-resident per-element state (relative to warp-region end)
        float4 As_reg[NCH];    // Asuf
        uint2  ms_reg[NCH];    // Msuf as 2x half2

        float4 Ar = make_float4(0.f, 0.f, 0.f, 0.f);
        float4 Mr = make_float4(1.f, 1.f, 1.f, 1.f);

        #pragma unroll
        for (int ch = NCH - 1; ch >= 0; --ch) {
            const int t = w * WT + ch * CHT + sl;
            const size_t o0 = base3 + (size_t)t * KK + kg * 4;

            // fully coalesced streaming loads (no q in phase 1)
            const float4 r4 = __ldcs((const float4*)(rw  + o0));
            const float4 v4 = __ldcs((const float4*)(tv  + o0 + KK));
            const float4 Q4 = __ldcs((const float4*)(tq  + o0 + KK));
            const float4 l4 = __ldcs((const float4*)(tlp + o0 + KK));
            const float  ol = olp[base2 + t + 1];

            const bool last = (t == SS - 1);
            const float sgn = last ? 1.0f : -1.0f;
            const float gm  = last ? 0.0f : GAMMA_F;

            float4 A, M;
            { float c = __expf(fminf(l4.x - ol, 0.f));
              A.x = fmaf(GAMMA_F, fmaf(sgn * c, Q4.x, v4.x), r4.x); M.x = gm * c; }
            { float c = __expf(fminf(l4.y - ol, 0.f));
              A.y = fmaf(GAMMA_F, fmaf(sgn * c, Q4.y, v4.y), r4.y); M.y = gm * c; }
            { float c = __expf(fminf(l4.z - ol, 0.f));
              A.z = fmaf(GAMMA_F, fmaf(sgn * c, Q4.z, v4.z), r4.z); M.z = gm * c; }
            { float c = __expf(fminf(l4.w - ol, 0.f));
              A.w = fmaf(GAMMA_F, fmaf(sgn * c, Q4.w, v4.w), r4.w); M.w = gm * c; }

            // warp suffix scan over 16 timesteps (lanes)
            #pragma unroll
            for (int d = 1; d < 16; d <<= 1) {
                float4 Ao, Mo;
                Ao.x = __shfl_down_sync(fullm, A.x, 2 * d);
                Ao.y = __shfl_down_sync(fullm, A.y, 2 * d);
                Ao.z = __shfl_down_sync(fullm, A.z, 2 * d);
                Ao.w = __shfl_down_sync(fullm, A.w, 2 * d);
                Mo.x = __shfl_down_sync(fullm, M.x, 2 * d);
                Mo.y = __shfl_down_sync(fullm, M.y, 2 * d);
                Mo.z = __shfl_down_sync(fullm, M.z, 2 * d);
                Mo.w = __shfl_down_sync(fullm, M.w, 2 * d);
                if (sl + d < 16) {
                    A.x = fmaf(M.x, Ao.x, A.x); M.x *= Mo.x;
                    A.y = fmaf(M.y, Ao.y, A.y); M.y *= Mo.y;
                    A.z = fmaf(M.z, Ao.z, A.z); M.z *= Mo.z;
                    A.w = fmaf(M.w, Ao.w, A.w); M.w *= Mo.w;
                }
            }

            // full-chunk transform lives in lanes 0/1
            float4 Af, Mf;
            Af.x = __shfl_sync(fullm, A.x, kg);
            Af.y = __shfl_sync(fullm, A.y, kg);
            Af.z = __shfl_sync(fullm, A.z, kg);
            Af.w = __shfl_sync(fullm, A.w, kg);
            Mf.x = __shfl_sync(fullm, M.x, kg);
            Mf.y = __shfl_sync(fullm, M.y, kg);
            Mf.z = __shfl_sync(fullm, M.z, kg);
            Mf.w = __shfl_sync(fullm, M.w, kg);

            // suffix relative to warp-region end
            float4 As, Ms;
            As.x = fmaf(M.x, Ar.x, A.x);  Ms.x = M.x * Mr.x;
            As.y = fmaf(M.y, Ar.y, A.y);  Ms.y = M.y * Mr.y;
            As.z = fmaf(M.z, Ar.z, A.z);  Ms.z = M.z * Mr.z;
            As.w = fmaf(M.w, Ar.w, A.w);  Ms.w = M.w * Mr.w;

            As_reg[ch] = As;
            __half2 h01 = __floats2half2_rn(Ms.x, Ms.y);
            __half2 h23 = __floats2half2_rn(Ms.z, Ms.w);
            ms_reg[ch].x = *(uint32_t*)&h01;
            ms_reg[ch].y = *(uint32_t*)&h23;

            Ar.x = fmaf(Mf.x, Ar.x, Af.x);  Mr.x *= Mf.x;
            Ar.y = fmaf(Mf.y, Ar.y, Af.y);  Mr.y *= Mf.y;
            Ar.z = fmaf(Mf.z, Ar.z, Af.z);  Mr.z *= Mf.z;
            Ar.w = fmaf(Mf.w, Ar.w, Af.w);  Mr.w *= Mf.w;
        }

        // warp totals -> smem buffer 0
        if (lane < 2) {
            *(float4*)(b0A + w * KK + kg * 4) = Ar;
            *(float4*)(b0M + w * KK + kg * 4) = Mr;
        }
        __syncthreads();

        // issue q loads NOW: they fly during the smem scan
        float4 q_reg[NCH];
        #pragma unroll
        for (int ch = 0; ch < NCH; ++ch) {
            const int t = w * WT + ch * CHT + sl;
            const size_t o0 = base3 + (size_t)t * KK + kg * 4;
            q_reg[ch] = __ldcs((const float4*)(q + o0));
        }

        // cooperative suffix scan over warp totals: S_w = T_w ∘ ... ∘ T_31
        #define SCAN_ROUND(SA, SM, DA, DM, D)                                 \
        do {                                                                  \
            if (tid < NW * KK) {                                              \
                const int ww = tid >> 3;                                      \
                float a = SA[tid], m = SM[tid];                               \
                if (ww + (D) < NW) {                                          \
                    a = fmaf(m, SA[tid + (D) * KK], a);                       \
                    m *= SM[tid + (D) * KK];                                  \
                }                                                             \
                DA[tid] = a; DM[tid] = m;                                     \
            }                                                                 \
            __syncthreads();                                                  \
        } while (0)

        SCAN_ROUND(b0A, b0M, b1A, b1M, 1);
        SCAN_ROUND(b1A, b1M, b0A, b0M, 2);
        SCAN_ROUND(b0A, b0M, b1A, b1M, 4);
        SCAN_ROUND(b1A, b1M, b0A, b0M, 8);
        SCAN_ROUND(b0A, b0M, b1A, b1M, 16);
        // inclusive suffix S_w now in b1A/b1M

        // carry at end of this warp's region (seed 0: CTA covers full row)
        float4 x4;
        if (w < NW - 1) {
            x4 = *(const float4*)(b1A + (w + 1) * KK + kg * 4);
        } else {
            x4 = make_float4(0.f, 0.f, 0.f, 0.f);
        }

        // Phase 2: d = q - (Asuf + Msuf * x4)
        #pragma unroll
        for (int ch = 0; ch < NCH; ++ch) {
            const float4 a4 = As_reg[ch];
            const float4 q4 = q_reg[ch];
            const float2 m01 = __half22float2(*(const __half2*)&ms_reg[ch].x);
            const float2 m23 = __half22float2(*(const __half2*)&ms_reg[ch].y);

            float d, ad;
            d = q4.x - fmaf(m01.x, x4.x, a4.x); ad = fabsf(d);
            lsum += (ad < 1.0f) ? 0.5f * d * d : (ad - 0.5f);
            d = q4.y - fmaf(m01.y, x4.y, a4.y); ad = fabsf(d);
            lsum += (ad < 1.0f) ? 0.5f * d * d : (ad - 0.5f);
            d = q4.z - fmaf(m23.x, x4.z, a4.z); ad = fabsf(d);
            lsum += (ad < 1.0f) ? 0.5f * d * d : (ad - 0.5f);
            d = q4.w - fmaf(m23.y, x4.w, a4.w); ad = fabsf(d);
            lsum += (ad < 1.0f) ? 0.5f * d * d : (ad - 0.5f);
        }
        // no trailing sync needed: loop-top __syncthreads protects s_row/smem reuse
    }

    // final reduce + atomic (once per CTA)
    #pragma unroll
    for (int off = 16; off > 0; off >>= 1)
        lsum += __shfl_down_sync(fullm, lsum, off);
    if (lane == 0) red[w] = lsum;
    __syncthreads();
    if (tid < 32) {
        float v = red[tid];
        #pragma unroll
        for (int off = 16; off > 0; off >>= 1)
            v += __shfl_down_sync(fullm, v, off);
        if (tid == 0)
            atomicAdd(out, v * (1.0f / 33554432.0f));   // mean over 2048*2048*8
    }
}

extern "C" void kernel_launch(void* const* d_in, const int* in_sizes, int n_in,
                              void* d_out, int out_size)
{
    (void)in_sizes; (void)n_in; (void)out_size;
    const float* q   = (const float*)d_in[0];
    const float* tq  = (const float*)d_in[1];
    const float* tv  = (const float*)d_in[2];
    const float* rw  = (const float*)d_in[3];
    const float* olp = (const float*)d_in[4];
    const float* tlp = (const float*)d_in[5];
    float* out = (float*)d_out;

    cudaFuncSetAttribute(retrace_loss_kernel,
                         cudaFuncAttributeMaxDynamicSharedMemorySize,
                         SMEM_BYTES);

    // reset row counter + output accumulator (graph-capturable, no allocation)
    void* ctr_addr = nullptr;
    cudaGetSymbolAddress(&ctr_addr, g_row_counter);
    cudaMemsetAsync(ctr_addr, 0, sizeof(unsigned int));
    cudaMemsetAsync(out, 0, sizeof(float));

    retrace_loss_kernel<<<GRID, NTH, SMEM_BYTES>>>(q, tq, tv, rw, olp, tlp, out);
}